// round 3
// baseline (speedup 1.0000x reference)
#include <cuda_runtime.h>
#include <cstdint>
#include <math.h>

// Problem constants
#define BB   64
#define TT   256
#define DD   512
#define HH   1024
#define GG   4096   // 4*H
#define NCTA2 128   // persistent recurrent kernel grid size

// ---------------- device scratch (static allocation; no cudaMalloc allowed) ---
__device__ float g_gates[(size_t)TT * BB * GG];   // 268 MB: precomputed x@W_ih^T + biases
__device__ float g_h[BB * HH];
__device__ float g_c[BB * HH];
__device__ float g_gbuf[BB * GG];                 // per-step gate buffer
__device__ int   g_perm[BB];                      // batch order sorted by length desc
__device__ int   g_act[TT];                       // # active rows at step t
__device__ int   g_is64;                          // tokens/lengths are int64?
__device__ unsigned g_cnt = 0;                    // grid barrier counter
__device__ unsigned g_gen = 0;                    // grid barrier generation (monotone)

// ---------------- grid barrier (sense via monotone generation) ----------------
__device__ __forceinline__ void grid_barrier(unsigned& gen)
{
    __syncthreads();
    gen++;
    if (threadIdx.x == 0) {
        __threadfence();
        unsigned prev = atomicAdd(&g_cnt, 1u);
        if (prev == NCTA2 - 1) {
            atomicExch(&g_cnt, 0u);
            __threadfence();
            atomicExch(&g_gen, gen);
        } else {
            while (*((volatile unsigned*)&g_gen) < gen) { }
            __threadfence();
        }
    }
    __syncthreads();
}

// ---------------- prep: detect int width, sort batches by length desc ---------
__global__ void k_prep(const int* __restrict__ len32)
{
    // lengths >= 1 always. If int64 layout, l32[1] is the high word of
    // lengths[0] (== 0). If int32 layout, l32[1] = lengths[1] >= 1.
    int is64 = (len32[1] == 0) ? 1 : 0;
    g_is64 = is64;

    int perm[BB];
    int len[BB];
    for (int i = 0; i < BB; i++) {
        perm[i] = i;
        len[i]  = is64 ? len32[2 * i] : len32[i];   // values < 2^31: low word ok
    }
    // selection sort, descending by length
    for (int i = 0; i < BB; i++) {
        int best = i;
        for (int j = i + 1; j < BB; j++)
            if (len[j] > len[best]) best = j;
        int tl = len[i];  len[i]  = len[best];  len[best]  = tl;
        int tp = perm[i]; perm[i] = perm[best]; perm[best] = tp;
    }
    for (int i = 0; i < BB; i++) g_perm[i] = perm[i];
    for (int t = 0; t < TT; t++) {
        int cnt = 0;
        for (int i = 0; i < BB; i++) if (len[i] > t) cnt++;
        g_act[t] = cnt;
    }
}

// ---------------- phase 1: gates_x[t][i][n] = emb[tok] @ W_ih^T + b_ih + b_hh --
// CTA: 64 rows (one t, sorted batch order) x 64 cols. 256 threads, 4x4 micro,
// k-tile 16, double-buffered smem.
__global__ __launch_bounds__(256, 1) void k_input_gemm(
    const int*   __restrict__ tok32,
    const float* __restrict__ emb,
    const float* __restrict__ W_ih,
    const float* __restrict__ b_ih,
    const float* __restrict__ b_hh)
{
    const int t    = blockIdx.y;
    const int n0   = blockIdx.x * 64;
    const int Mact = g_act[t];
    if (Mact == 0) return;

    __shared__ __align__(16) float Xs[2][16][68];
    __shared__ __align__(16) float Ws[2][16][68];
    __shared__ int s_tok[BB];

    const int tid = threadIdx.x;
    if (tid < BB) {
        int b = g_perm[tid];
        size_t off = (size_t)b * TT + t;
        s_tok[tid] = g_is64 ? tok32[2 * off] : tok32[off];
    }
    __syncthreads();

    const int tx = tid & 15;
    const int ty = tid >> 4;
    const int m0 = ty * 4;
    const bool rowact = (m0 < Mact);

    float acc[4][4];
#pragma unroll
    for (int r = 0; r < 4; r++)
#pragma unroll
        for (int c = 0; c < 4; c++) acc[r][c] = 0.f;

    int lm[4], lk[4];
#pragma unroll
    for (int v = 0; v < 4; v++) { int e = tid + 256 * v; lm[v] = e >> 4; lk[v] = e & 15; }

    float xr[4], wr[4];
#pragma unroll
    for (int v = 0; v < 4; v++) {
        xr[v] = (lm[v] < Mact) ? emb[(size_t)s_tok[lm[v]] * DD + lk[v]] : 0.f;
        wr[v] = W_ih[(size_t)(n0 + lm[v]) * DD + lk[v]];
    }
#pragma unroll
    for (int v = 0; v < 4; v++) { Xs[0][lk[v]][lm[v]] = xr[v]; Ws[0][lk[v]][lm[v]] = wr[v]; }
    __syncthreads();

    const int NKT = DD / 16;  // 32
    for (int kt = 0; kt < NKT; kt++) {
        const int p = kt & 1;
        if (kt + 1 < NKT) {
            const int k0 = (kt + 1) * 16;
#pragma unroll
            for (int v = 0; v < 4; v++) {
                xr[v] = (lm[v] < Mact) ? emb[(size_t)s_tok[lm[v]] * DD + k0 + lk[v]] : 0.f;
                wr[v] = W_ih[(size_t)(n0 + lm[v]) * DD + k0 + lk[v]];
            }
        }
        if (rowact) {
#pragma unroll
            for (int kk = 0; kk < 16; kk++) {
                float4 a = *(const float4*)&Xs[p][kk][m0];
                float4 b = *(const float4*)&Ws[p][kk][tx * 4];
                acc[0][0] += a.x * b.x; acc[0][1] += a.x * b.y; acc[0][2] += a.x * b.z; acc[0][3] += a.x * b.w;
                acc[1][0] += a.y * b.x; acc[1][1] += a.y * b.y; acc[1][2] += a.y * b.z; acc[1][3] += a.y * b.w;
                acc[2][0] += a.z * b.x; acc[2][1] += a.z * b.y; acc[2][2] += a.z * b.z; acc[2][3] += a.z * b.w;
                acc[3][0] += a.w * b.x; acc[3][1] += a.w * b.y; acc[3][2] += a.w * b.z; acc[3][3] += a.w * b.w;
            }
        }
        if (kt + 1 < NKT) {
            const int q = (kt + 1) & 1;
#pragma unroll
            for (int v = 0; v < 4; v++) { Xs[q][lk[v]][lm[v]] = xr[v]; Ws[q][lk[v]][lm[v]] = wr[v]; }
            __syncthreads();
        }
    }

    if (rowact) {
        const int n = n0 + tx * 4;
        float bx = b_ih[n + 0] + b_hh[n + 0];
        float by = b_ih[n + 1] + b_hh[n + 1];
        float bz = b_ih[n + 2] + b_hh[n + 2];
        float bw = b_ih[n + 3] + b_hh[n + 3];
#pragma unroll
        for (int r = 0; r < 4; r++) {
            int m = m0 + r;
            if (m < Mact) {
                float4 o = make_float4(acc[r][0] + bx, acc[r][1] + by,
                                       acc[r][2] + bz, acc[r][3] + bw);
                *(float4*)&g_gates[((size_t)t * BB + m) * GG + n] = o;
            }
        }
    }
}

// ---------------- phase 2: persistent recurrent kernel ------------------------
// 128 CTAs x 256 threads. Each CTA owns a 32-column slice of the 4096 gate
// columns. Per step: gbuf = gates_x[t] + h @ W_hh^T (64x32 tile, K=1024,
// double-buffered smem, 4x2 micro), grid barrier, elementwise LSTM update,
// grid barrier. Cross-CTA global reads use __ldcg (L1 is not coherent).
__global__ __launch_bounds__(256, 1) void k_recurrent(
    const float* __restrict__ W_hh,
    float*       __restrict__ out)
{
    __shared__ __align__(16) float hs[2][32][68];
    __shared__ __align__(16) float Wsh[2][32][34];
    __shared__ int s_act[TT];
    __shared__ int s_perm[BB];
    __shared__ unsigned s_base;

    const int tid = threadIdx.x;
    const int cta = blockIdx.x;
    const int n0  = cta * 32;

    if (tid < TT) s_act[tid] = g_act[tid];
    if (tid < BB) s_perm[tid] = g_perm[tid];
    if (tid == 0) s_base = *((volatile unsigned*)&g_gen);

    // zero h, c (mapping idx -> cta is fixed; g_c stays CTA-private for L1)
    for (int idx = cta * 256 + tid; idx < BB * HH; idx += NCTA2 * 256) {
        g_h[idx] = 0.f;
        g_c[idx] = 0.f;
    }
    __syncthreads();
    unsigned gen = s_base;
    grid_barrier(gen);   // h/c zeroed + visible everywhere

    const int tx = tid & 15;
    const int ty = tid >> 4;
    const int m0 = ty * 4;
    const int j0 = tx * 2;

    for (int t = 0; t < TT; t++) {
        const int Mact = s_act[t];
        if (Mact == 0) break;            // act[] non-increasing: consistent break
        const bool rowact = (m0 < Mact);

        float acc[4][2];
#pragma unroll
        for (int r = 0; r < 4; r++) { acc[r][0] = 0.f; acc[r][1] = 0.f; }

        float hr[8], wr2[4];
#pragma unroll
        for (int v = 0; v < 8; v++) {
            int e = tid + 256 * v; int m = e >> 5; int kk = e & 31;
            hr[v] = (m < Mact) ? __ldcg(&g_h[m * HH + kk]) : 0.f;
        }
#pragma unroll
        for (int v = 0; v < 4; v++) {
            int e = tid + 256 * v; int j = e >> 5; int kk = e & 31;
            wr2[v] = W_hh[(size_t)(n0 + j) * HH + kk];
        }
#pragma unroll
        for (int v = 0; v < 8; v++) { int e = tid + 256 * v; hs[0][e & 31][e >> 5] = hr[v]; }
#pragma unroll
        for (int v = 0; v < 4; v++) { int e = tid + 256 * v; Wsh[0][e & 31][e >> 5] = wr2[v]; }
        __syncthreads();

        const int NKT = HH / 32;  // 32
        for (int kt = 0; kt < NKT; kt++) {
            const int p = kt & 1;
            if (kt + 1 < NKT) {
                const int k0 = (kt + 1) * 32;
#pragma unroll
                for (int v = 0; v < 8; v++) {
                    int e = tid + 256 * v; int m = e >> 5; int kk = e & 31;
                    hr[v] = (m < Mact) ? __ldcg(&g_h[m * HH + k0 + kk]) : 0.f;
                }
#pragma unroll
                for (int v = 0; v < 4; v++) {
                    int e = tid + 256 * v; int j = e >> 5; int kk = e & 31;
                    wr2[v] = W_hh[(size_t)(n0 + j) * HH + k0 + kk];
                }
            }
            if (rowact) {
#pragma unroll
                for (int kk = 0; kk < 32; kk++) {
                    float4 a = *(const float4*)&hs[p][kk][m0];
                    float2 b = *(const float2*)&Wsh[p][kk][j0];
                    acc[0][0] += a.x * b.x; acc[0][1] += a.x * b.y;
                    acc[1][0] += a.y * b.x; acc[1][1] += a.y * b.y;
                    acc[2][0] += a.z * b.x; acc[2][1] += a.z * b.y;
                    acc[3][0] += a.w * b.x; acc[3][1] += a.w * b.y;
                }
            }
            if (kt + 1 < NKT) {
                const int q = (kt + 1) & 1;
#pragma unroll
                for (int v = 0; v < 8; v++) { int e = tid + 256 * v; hs[q][e & 31][e >> 5] = hr[v]; }
#pragma unroll
                for (int v = 0; v < 4; v++) { int e = tid + 256 * v; Wsh[q][e & 31][e >> 5] = wr2[v]; }
                __syncthreads();
            }
        }

        if (rowact) {
#pragma unroll
            for (int r = 0; r < 4; r++) {
                int m = m0 + r;
                if (m < Mact) {
                    size_t gidx = ((size_t)t * BB + m) * GG + n0 + j0;
                    float2 gx = *(const float2*)&g_gates[gidx];
                    float2 o  = make_float2(acc[r][0] + gx.x, acc[r][1] + gx.y);
                    *(float2*)&g_gbuf[m * GG + n0 + j0] = o;
                }
            }
        }
        grid_barrier(gen);

        // elementwise LSTM update (idx -> cta mapping fixed: g_c CTA-private)
        for (int idx = cta * 256 + tid; idx < Mact * HH; idx += NCTA2 * 256) {
            int i  = idx >> 10;
            int hc = idx & (HH - 1);
            float ig = __ldcg(&g_gbuf[i * GG + hc]);
            float fg = __ldcg(&g_gbuf[i * GG + HH + hc]);
            float gg = __ldcg(&g_gbuf[i * GG + 2 * HH + hc]);
            float og = __ldcg(&g_gbuf[i * GG + 3 * HH + hc]);
            float is = 1.f / (1.f + expf(-ig));
            float fs = 1.f / (1.f + expf(-fg));
            float gt = tanhf(gg);
            float os = 1.f / (1.f + expf(-og));
            float cn = fs * g_c[idx] + is * gt;
            g_c[idx] = cn;
            g_h[idx] = os * tanhf(cn);
        }
        grid_barrier(gen);
    }

    // scatter h back to original batch order (same idx mapping as the updates,
    // so g_h[idx] was written by this CTA — plain load is safe)
    for (int idx = cta * 256 + tid; idx < BB * HH; idx += NCTA2 * 256) {
        int i  = idx >> 10;
        int hc = idx & (HH - 1);
        out[(size_t)s_perm[i] * HH + hc] = g_h[idx];
    }
}

// ---------------- launch -------------------------------------------------------
extern "C" void kernel_launch(void* const* d_in, const int* in_sizes, int n_in,
                              void* d_out, int out_size)
{
    const int*   tokens  = (const int*)  d_in[0];  // int32 or int64 (autodetected)
    const int*   lengths = (const int*)  d_in[1];
    const float* emb     = (const float*)d_in[2];
    const float* W_ih    = (const float*)d_in[3];
    const float* W_hh    = (const float*)d_in[4];
    const float* b_ih    = (const float*)d_in[5];
    const float* b_hh    = (const float*)d_in[6];
    float* out = (float*)d_out;

    k_prep<<<1, 1>>>(lengths);

    dim3 g1(GG / 64, TT);
    k_input_gemm<<<g1, 256>>>(tokens, emb, W_ih, b_ih, b_hh);

    k_recurrent<<<NCTA2, 256>>>(W_hh, out);
}

// round 4
// speedup vs baseline: 1.0046x; 1.0046x over previous
#include <cuda_runtime.h>
#include <cstdint>
#include <math.h>

// Problem constants
#define BB   64
#define TT   256
#define DD   512
#define HH   1024
#define GG   4096   // 4*H
#define NCTA2 128   // persistent recurrent kernel grid size

// ---------------- device scratch (static allocation; no cudaMalloc allowed) ---
__device__ float g_gates[(size_t)TT * BB * GG];   // 268 MB: precomputed x@W_ih^T + biases
__device__ float g_h[BB * HH];
__device__ float g_c[BB * HH];
__device__ float g_gbuf[BB * GG];                 // per-step gate buffer
__device__ int   g_perm[BB];                      // batch order sorted by length desc
__device__ int   g_act[TT];                       // # active rows at step t
__device__ int   g_is64;                          // tokens/lengths are int64?
__device__ unsigned g_cnt = 0;                    // grid barrier counter
__device__ unsigned g_gen = 0;                    // grid barrier generation (monotone)

// ---------------- grid barrier (sense via monotone generation) ----------------
__device__ __forceinline__ void grid_barrier(unsigned& gen)
{
    __syncthreads();
    gen++;
    if (threadIdx.x == 0) {
        __threadfence();
        unsigned prev = atomicAdd(&g_cnt, 1u);
        if (prev == NCTA2 - 1) {
            atomicExch(&g_cnt, 0u);
            __threadfence();
            atomicExch(&g_gen, gen);
        } else {
            while (*((volatile unsigned*)&g_gen) < gen) { }
            __threadfence();
        }
    }
    __syncthreads();
}

// ---------------- prep: detect int width, sort batches by length desc ---------
__global__ void k_prep(const int* __restrict__ len32)
{
    // lengths >= 1 always. If int64 layout, l32[1] is the high word of
    // lengths[0] (== 0). If int32 layout, l32[1] = lengths[1] >= 1.
    int is64 = (len32[1] == 0) ? 1 : 0;
    g_is64 = is64;

    int perm[BB];
    int len[BB];
    for (int i = 0; i < BB; i++) {
        perm[i] = i;
        len[i]  = is64 ? len32[2 * i] : len32[i];   // values < 2^31: low word ok
    }
    // selection sort, descending by length
    for (int i = 0; i < BB; i++) {
        int best = i;
        for (int j = i + 1; j < BB; j++)
            if (len[j] > len[best]) best = j;
        int tl = len[i];  len[i]  = len[best];  len[best]  = tl;
        int tp = perm[i]; perm[i] = perm[best]; perm[best] = tp;
    }
    for (int i = 0; i < BB; i++) g_perm[i] = perm[i];
    for (int t = 0; t < TT; t++) {
        int cnt = 0;
        for (int i = 0; i < BB; i++) if (len[i] > t) cnt++;
        g_act[t] = cnt;
    }
}

// ---------------- phase 1: gates_x[t][i][n] = emb[tok] @ W_ih^T + b_ih + b_hh --
// CTA: 64 rows (one t, sorted batch order) x 64 cols. 256 threads, 4x4 micro,
// k-tile 16, double-buffered smem.
__global__ __launch_bounds__(256, 1) void k_input_gemm(
    const int*   __restrict__ tok32,
    const float* __restrict__ emb,
    const float* __restrict__ W_ih,
    const float* __restrict__ b_ih,
    const float* __restrict__ b_hh)
{
    const int t    = blockIdx.y;
    const int n0   = blockIdx.x * 64;
    const int Mact = g_act[t];
    if (Mact == 0) return;

    __shared__ __align__(16) float Xs[2][16][68];
    __shared__ __align__(16) float Ws[2][16][68];
    __shared__ int s_tok[BB];

    const int tid = threadIdx.x;
    if (tid < BB) {
        int b = g_perm[tid];
        size_t off = (size_t)b * TT + t;
        s_tok[tid] = g_is64 ? tok32[2 * off] : tok32[off];
    }
    __syncthreads();

    const int tx = tid & 15;
    const int ty = tid >> 4;
    const int m0 = ty * 4;
    const bool rowact = (m0 < Mact);

    float acc[4][4];
#pragma unroll
    for (int r = 0; r < 4; r++)
#pragma unroll
        for (int c = 0; c < 4; c++) acc[r][c] = 0.f;

    int lm[4], lk[4];
#pragma unroll
    for (int v = 0; v < 4; v++) { int e = tid + 256 * v; lm[v] = e >> 4; lk[v] = e & 15; }

    float xr[4], wr[4];
#pragma unroll
    for (int v = 0; v < 4; v++) {
        xr[v] = (lm[v] < Mact) ? emb[(size_t)s_tok[lm[v]] * DD + lk[v]] : 0.f;
        wr[v] = W_ih[(size_t)(n0 + lm[v]) * DD + lk[v]];
    }
#pragma unroll
    for (int v = 0; v < 4; v++) { Xs[0][lk[v]][lm[v]] = xr[v]; Ws[0][lk[v]][lm[v]] = wr[v]; }
    __syncthreads();

    const int NKT = DD / 16;  // 32
    for (int kt = 0; kt < NKT; kt++) {
        const int p = kt & 1;
        if (kt + 1 < NKT) {
            const int k0 = (kt + 1) * 16;
#pragma unroll
            for (int v = 0; v < 4; v++) {
                xr[v] = (lm[v] < Mact) ? emb[(size_t)s_tok[lm[v]] * DD + k0 + lk[v]] : 0.f;
                wr[v] = W_ih[(size_t)(n0 + lm[v]) * DD + k0 + lk[v]];
            }
        }
        if (rowact) {
#pragma unroll
            for (int kk = 0; kk < 16; kk++) {
                float4 a = *(const float4*)&Xs[p][kk][m0];
                float4 b = *(const float4*)&Ws[p][kk][tx * 4];
                acc[0][0] += a.x * b.x; acc[0][1] += a.x * b.y; acc[0][2] += a.x * b.z; acc[0][3] += a.x * b.w;
                acc[1][0] += a.y * b.x; acc[1][1] += a.y * b.y; acc[1][2] += a.y * b.z; acc[1][3] += a.y * b.w;
                acc[2][0] += a.z * b.x; acc[2][1] += a.z * b.y; acc[2][2] += a.z * b.z; acc[2][3] += a.z * b.w;
                acc[3][0] += a.w * b.x; acc[3][1] += a.w * b.y; acc[3][2] += a.w * b.z; acc[3][3] += a.w * b.w;
            }
        }
        if (kt + 1 < NKT) {
            const int q = (kt + 1) & 1;
#pragma unroll
            for (int v = 0; v < 4; v++) { Xs[q][lk[v]][lm[v]] = xr[v]; Ws[q][lk[v]][lm[v]] = wr[v]; }
            __syncthreads();
        }
    }

    if (rowact) {
        const int n = n0 + tx * 4;
        float bx = b_ih[n + 0] + b_hh[n + 0];
        float by = b_ih[n + 1] + b_hh[n + 1];
        float bz = b_ih[n + 2] + b_hh[n + 2];
        float bw = b_ih[n + 3] + b_hh[n + 3];
#pragma unroll
        for (int r = 0; r < 4; r++) {
            int m = m0 + r;
            if (m < Mact) {
                float4 o = make_float4(acc[r][0] + bx, acc[r][1] + by,
                                       acc[r][2] + bz, acc[r][3] + bw);
                *(float4*)&g_gates[((size_t)t * BB + m) * GG + n] = o;
            }
        }
    }
}

// ---------------- phase 2: persistent recurrent kernel ------------------------
// 128 CTAs x 256 threads. Each CTA owns a 32-column slice of the 4096 gate
// columns. Per step: gbuf = gates_x[t] + h @ W_hh^T (64x32 tile, K=1024,
// double-buffered smem, 4x2 micro), grid barrier, elementwise LSTM update,
// grid barrier. Cross-CTA global reads use __ldcg (L1 is not coherent).
__global__ __launch_bounds__(256, 1) void k_recurrent(
    const float* __restrict__ W_hh,
    float*       __restrict__ out)
{
    __shared__ __align__(16) float hs[2][32][68];
    __shared__ __align__(16) float Wsh[2][32][34];
    __shared__ int s_act[TT];
    __shared__ int s_perm[BB];
    __shared__ unsigned s_base;

    const int tid = threadIdx.x;
    const int cta = blockIdx.x;
    const int n0  = cta * 32;

    if (tid < TT) s_act[tid] = g_act[tid];
    if (tid < BB) s_perm[tid] = g_perm[tid];
    if (tid == 0) s_base = *((volatile unsigned*)&g_gen);

    // zero h, c (mapping idx -> cta is fixed; g_c stays CTA-private for L1)
    for (int idx = cta * 256 + tid; idx < BB * HH; idx += NCTA2 * 256) {
        g_h[idx] = 0.f;
        g_c[idx] = 0.f;
    }
    __syncthreads();
    unsigned gen = s_base;
    grid_barrier(gen);   // h/c zeroed + visible everywhere

    const int tx = tid & 15;
    const int ty = tid >> 4;
    const int m0 = ty * 4;
    const int j0 = tx * 2;

    for (int t = 0; t < TT; t++) {
        const int Mact = s_act[t];
        if (Mact == 0) break;            // act[] non-increasing: consistent break
        const bool rowact = (m0 < Mact);

        float acc[4][2];
#pragma unroll
        for (int r = 0; r < 4; r++) { acc[r][0] = 0.f; acc[r][1] = 0.f; }

        float hr[8], wr2[4];
#pragma unroll
        for (int v = 0; v < 8; v++) {
            int e = tid + 256 * v; int m = e >> 5; int kk = e & 31;
            hr[v] = (m < Mact) ? __ldcg(&g_h[m * HH + kk]) : 0.f;
        }
#pragma unroll
        for (int v = 0; v < 4; v++) {
            int e = tid + 256 * v; int j = e >> 5; int kk = e & 31;
            wr2[v] = W_hh[(size_t)(n0 + j) * HH + kk];
        }
#pragma unroll
        for (int v = 0; v < 8; v++) { int e = tid + 256 * v; hs[0][e & 31][e >> 5] = hr[v]; }
#pragma unroll
        for (int v = 0; v < 4; v++) { int e = tid + 256 * v; Wsh[0][e & 31][e >> 5] = wr2[v]; }
        __syncthreads();

        const int NKT = HH / 32;  // 32
        for (int kt = 0; kt < NKT; kt++) {
            const int p = kt & 1;
            if (kt + 1 < NKT) {
                const int k0 = (kt + 1) * 32;
#pragma unroll
                for (int v = 0; v < 8; v++) {
                    int e = tid + 256 * v; int m = e >> 5; int kk = e & 31;
                    hr[v] = (m < Mact) ? __ldcg(&g_h[m * HH + k0 + kk]) : 0.f;
                }
#pragma unroll
                for (int v = 0; v < 4; v++) {
                    int e = tid + 256 * v; int j = e >> 5; int kk = e & 31;
                    wr2[v] = W_hh[(size_t)(n0 + j) * HH + k0 + kk];
                }
            }
            if (rowact) {
#pragma unroll
                for (int kk = 0; kk < 32; kk++) {
                    float4 a = *(const float4*)&hs[p][kk][m0];
                    float2 b = *(const float2*)&Wsh[p][kk][j0];
                    acc[0][0] += a.x * b.x; acc[0][1] += a.x * b.y;
                    acc[1][0] += a.y * b.x; acc[1][1] += a.y * b.y;
                    acc[2][0] += a.z * b.x; acc[2][1] += a.z * b.y;
                    acc[3][0] += a.w * b.x; acc[3][1] += a.w * b.y;
                }
            }
            if (kt + 1 < NKT) {
                const int q = (kt + 1) & 1;
#pragma unroll
                for (int v = 0; v < 8; v++) { int e = tid + 256 * v; hs[q][e & 31][e >> 5] = hr[v]; }
#pragma unroll
                for (int v = 0; v < 4; v++) { int e = tid + 256 * v; Wsh[q][e & 31][e >> 5] = wr2[v]; }
                __syncthreads();
            }
        }

        if (rowact) {
#pragma unroll
            for (int r = 0; r < 4; r++) {
                int m = m0 + r;
                if (m < Mact) {
                    size_t gidx = ((size_t)t * BB + m) * GG + n0 + j0;
                    float2 gx = *(const float2*)&g_gates[gidx];
                    float2 o  = make_float2(acc[r][0] + gx.x, acc[r][1] + gx.y);
                    *(float2*)&g_gbuf[m * GG + n0 + j0] = o;
                }
            }
        }
        grid_barrier(gen);

        // elementwise LSTM update (idx -> cta mapping fixed: g_c CTA-private)
        for (int idx = cta * 256 + tid; idx < Mact * HH; idx += NCTA2 * 256) {
            int i  = idx >> 10;
            int hc = idx & (HH - 1);
            float ig = __ldcg(&g_gbuf[i * GG + hc]);
            float fg = __ldcg(&g_gbuf[i * GG + HH + hc]);
            float gg = __ldcg(&g_gbuf[i * GG + 2 * HH + hc]);
            float og = __ldcg(&g_gbuf[i * GG + 3 * HH + hc]);
            float is = 1.f / (1.f + expf(-ig));
            float fs = 1.f / (1.f + expf(-fg));
            float gt = tanhf(gg);
            float os = 1.f / (1.f + expf(-og));
            float cn = fs * g_c[idx] + is * gt;
            g_c[idx] = cn;
            g_h[idx] = os * tanhf(cn);
        }
        grid_barrier(gen);
    }

    // scatter h back to original batch order (same idx mapping as the updates,
    // so g_h[idx] was written by this CTA — plain load is safe)
    for (int idx = cta * 256 + tid; idx < BB * HH; idx += NCTA2 * 256) {
        int i  = idx >> 10;
        int hc = idx & (HH - 1);
        out[(size_t)s_perm[i] * HH + hc] = g_h[idx];
    }
}

// ---------------- launch -------------------------------------------------------
extern "C" void kernel_launch(void* const* d_in, const int* in_sizes, int n_in,
                              void* d_out, int out_size)
{
    const int*   tokens  = (const int*)  d_in[0];  // int32 or int64 (autodetected)
    const int*   lengths = (const int*)  d_in[1];
    const float* emb     = (const float*)d_in[2];
    const float* W_ih    = (const float*)d_in[3];
    const float* W_hh    = (const float*)d_in[4];
    const float* b_ih    = (const float*)d_in[5];
    const float* b_hh    = (const float*)d_in[6];
    float* out = (float*)d_out;

    k_prep<<<1, 1>>>(lengths);

    dim3 g1(GG / 64, TT);
    k_input_gemm<<<g1, 256>>>(tokens, emb, W_ih, b_ih, b_hh);

    k_recurrent<<<NCTA2, 256>>>(W_hh, out);
}